// round 2
// baseline (speedup 1.0000x reference)
#include <cuda_runtime.h>

#define ADAPT  32
#define T_LEN  2048
#define NCH    (T_LEN / ADAPT)   // 64 chunks per batch row
#define NWARP  8
#define CHW    (NCH / NWARP)     // 8 chunks per warp

// ---------------------------------------------------------------------------
// Fused kernel: one block per batch row.
//  Phase A (parallel, DRAM-bound): each warp processes 8 chunks:
//    coalesced float4 loads -> XOR-swizzled smem transpose -> per-step dot
//    with quant_bins (kept in regs) + chunk means (mdot, mg) to smem.
//  Phase B (tiny): warp 0 affine-scans the 64-chunk recurrence
//    (S,P) -> (S*mg, P + S*mdot).
//  Phase C: every lane writes out = P[c] + S[c]*dot directly from registers.
// ---------------------------------------------------------------------------
__global__ void __launch_bounds__(256, 1)
fused_dequant(const float* __restrict__ x,
              const float* __restrict__ qb,
              const float* __restrict__ cs,
              float* __restrict__ out)
{
    __shared__ float4 tile4[NWARP][32 * 8];  // per-warp 32x32 transpose buf (32 KB)
    __shared__ float  s_md[NCH], s_mg[NCH];  // per-chunk mean(dot), mean(g)
    __shared__ float  sP[NCH], sS[NCH];      // exclusive scan results
    __shared__ float4 s_qb[8], s_cs[8];

    const int tid  = threadIdx.x;
    const int w    = tid >> 5;
    const int lane = tid & 31;
    const int b    = blockIdx.x;

    if (tid < 8)        s_qb[tid]     = reinterpret_cast<const float4*>(qb)[tid];
    else if (tid < 16)  s_cs[tid - 8] = reinterpret_cast<const float4*>(cs)[tid - 8];
    __syncthreads();

    // batch row = 2048*32 floats = 16384 float4; chunk = 256 float4
    const float4* xb = reinterpret_cast<const float4*>(x) + (size_t)b * 16384;
    float4* tb = tile4[w];

    float dv[CHW];   // dot value for step s=lane of each owned chunk

#pragma unroll
    for (int i = 0; i < CHW; i++) {
        const int c = w * CHW + i;
        const float4* xp = xb + c * 256;

        float4 v[8];
#pragma unroll
        for (int k = 0; k < 8; k++) v[k] = xp[lane + 32 * k];

        __syncwarp();   // prior iteration's LDS reads done before overwrite
#pragma unroll
        for (int k = 0; k < 8; k++) {
            const int s = (lane >> 3) + 4 * k;   // step row
            const int j = lane & 7;              // col quad
            tb[s * 8 + (j ^ (s & 7))] = v[k];
        }
        __syncwarp();

        // lane = step s: two 32-wide dot products (conflict-free swizzled reads)
        float dotv = 0.f, gv = 0.f;
#pragma unroll
        for (int j = 0; j < 8; j++) {
            const float4 q  = tb[lane * 8 + (j ^ (lane & 7))];
            const float4 b4 = s_qb[j];
            const float4 c4 = s_cs[j];
            dotv += q.x * b4.x + q.y * b4.y + q.z * b4.z + q.w * b4.w;
            gv   += q.x * c4.x + q.y * c4.y + q.z * c4.z + q.w * c4.w;
        }
        dv[i] = dotv;

        float md = dotv, mg = gv;
#pragma unroll
        for (int off = 16; off; off >>= 1) {
            md += __shfl_xor_sync(0xffffffffu, md, off);
            mg += __shfl_xor_sync(0xffffffffu, mg, off);
        }
        if (lane == 0) {
            s_md[c] = md * (1.f / ADAPT);
            s_mg[c] = mg * (1.f / ADAPT);
        }
    }
    __syncthreads();

    // ---- Phase B: affine scan of 64 chunks in warp 0 (2 chunks per lane) ----
    if (tid < 32) {
        const float md0 = s_md[2 * lane],     md1 = s_md[2 * lane + 1];
        const float mg0 = s_mg[2 * lane],     mg1 = s_mg[2 * lane + 1];

        // segment composition: entering (S,P) -> (S*g, P + S*d)
        float g = mg0 * mg1;
        float d = md0 + mg0 * md1;

#pragma unroll
        for (int off = 1; off < 32; off <<= 1) {
            const float gp = __shfl_up_sync(0xffffffffu, g, off);
            const float dp = __shfl_up_sync(0xffffffffu, d, off);
            if (lane >= off) { d = dp + gp * d; g = gp * g; }
        }
        float Se = __shfl_up_sync(0xffffffffu, g, 1);
        float Pe = __shfl_up_sync(0xffffffffu, d, 1);
        if (lane == 0) { Se = 1.f; Pe = 0.f; }

        sS[2 * lane]     = Se;
        sP[2 * lane]     = Pe;
        sS[2 * lane + 1] = Se * mg0;
        sP[2 * lane + 1] = Pe + Se * md0;
    }
    __syncthreads();

    // ---- Phase C: write output straight from registers ----
    float* ob = out + (size_t)b * T_LEN;
#pragma unroll
    for (int i = 0; i < CHW; i++) {
        const int c = w * CHW + i;
        ob[c * ADAPT + lane] = sP[c] + sS[c] * dv[i];
    }
}

// ---------------------------------------------------------------------------
extern "C" void kernel_launch(void* const* d_in, const int* in_sizes, int n_in,
                              void* d_out, int out_size)
{
    const float* x  = (const float*)d_in[0];   // (B, T, NB) fp32
    const float* qb = (const float*)d_in[1];   // (NB,)
    const float* cs = (const float*)d_in[2];   // (NB, 1)
    float* out      = (float*)d_out;           // (B, T) fp32

    const int B = out_size / T_LEN;
    fused_dequant<<<B, 256>>>(x, qb, cs, out);
}

// round 3
// speedup vs baseline: 1.2638x; 1.2638x over previous
#include <cuda_runtime.h>

#define ADAPT  32
#define T_LEN  2048
#define NCH    (T_LEN / ADAPT)    // 64 chunks per batch row

// ---------------------------------------------------------------------------
// One block (256 threads) per batch row. Occupancy-first design:
//  Phase A: thread t <-> (step s = t>>3, bin-quad j = t&7). Per chunk:
//    one coalesced LDG.128, dot vs qb4[j]/cs4[j], 3-step octet shfl-reduce
//    -> s_dot[c*32+s], s_g[c*32+s] in smem. No transpose, no reg staging.
//  Phase B: per-chunk means (8 warps x 8 chunks), then warp-0 affine scan
//    of the 64-chunk recurrence (S,P) -> (S*mg, P + S*mdot).
//  Phase C: out = P[c] + S[c]*dot, vectorized float4 from smem.
// ---------------------------------------------------------------------------
__global__ void __launch_bounds__(256, 8)
fused_dequant(const float4* __restrict__ x4,
              const float*  __restrict__ qb,
              const float*  __restrict__ cs,
              float*        __restrict__ out)
{
    __shared__ float s_dot[T_LEN];          // 8 KB
    __shared__ float s_g  [T_LEN];          // 8 KB
    __shared__ float s_md[NCH], s_mg[NCH];
    __shared__ float sP[NCH], sS[NCH];

    const int tid  = threadIdx.x;
    const int lane = tid & 31;
    const int w    = tid >> 5;
    const int j    = tid & 7;      // bin quad
    const int srow = tid >> 3;     // step within chunk (0..31)
    const int b    = blockIdx.x;

    const float4 b4 = reinterpret_cast<const float4*>(qb)[j];
    const float4 c4 = reinterpret_cast<const float4*>(cs)[j];

    // batch row = 2048*32 floats = 16384 float4; chunk = 256 float4
    const float4* xb = x4 + (size_t)b * 16384;

    // ---- Phase A ----
#pragma unroll 2
    for (int c = 0; c < NCH; c++) {
        const float4 q = xb[c * 256 + tid];
        float p = q.x * b4.x + q.y * b4.y + q.z * b4.z + q.w * b4.w;
        float g = q.x * c4.x + q.y * c4.y + q.z * c4.z + q.w * c4.w;
        p += __shfl_xor_sync(0xffffffffu, p, 1);
        g += __shfl_xor_sync(0xffffffffu, g, 1);
        p += __shfl_xor_sync(0xffffffffu, p, 2);
        g += __shfl_xor_sync(0xffffffffu, g, 2);
        p += __shfl_xor_sync(0xffffffffu, p, 4);
        g += __shfl_xor_sync(0xffffffffu, g, 4);
        if (j == 0) {
            s_dot[c * 32 + srow] = p;
            s_g  [c * 32 + srow] = g;
        }
    }
    __syncthreads();

    // ---- Phase B1: per-chunk means (warp w handles chunks 8w..8w+7) ----
#pragma unroll
    for (int i = 0; i < 8; i++) {
        const int c = w * 8 + i;
        float md = s_dot[c * 32 + lane];
        float mg = s_g  [c * 32 + lane];
#pragma unroll
        for (int off = 16; off; off >>= 1) {
            md += __shfl_xor_sync(0xffffffffu, md, off);
            mg += __shfl_xor_sync(0xffffffffu, mg, off);
        }
        if (lane == 0) {
            s_md[c] = md * (1.f / ADAPT);
            s_mg[c] = mg * (1.f / ADAPT);
        }
    }
    __syncthreads();

    // ---- Phase B2: affine scan of 64 chunks in warp 0 (2 chunks/lane) ----
    if (tid < 32) {
        const float md0 = s_md[2 * lane], md1 = s_md[2 * lane + 1];
        const float mg0 = s_mg[2 * lane], mg1 = s_mg[2 * lane + 1];

        float g = mg0 * mg1;            // segment: (S,P)->(S*g, P+S*d)
        float d = md0 + mg0 * md1;
#pragma unroll
        for (int off = 1; off < 32; off <<= 1) {
            const float gp = __shfl_up_sync(0xffffffffu, g, off);
            const float dp = __shfl_up_sync(0xffffffffu, d, off);
            if (lane >= off) { d = dp + gp * d; g = gp * g; }
        }
        float Se = __shfl_up_sync(0xffffffffu, g, 1);
        float Pe = __shfl_up_sync(0xffffffffu, d, 1);
        if (lane == 0) { Se = 1.f; Pe = 0.f; }

        sS[2 * lane]     = Se;
        sP[2 * lane]     = Pe;
        sS[2 * lane + 1] = Se * mg0;
        sP[2 * lane + 1] = Pe + Se * md0;
    }
    __syncthreads();

    // ---- Phase C: vectorized output ----
    const float4* sd4 = reinterpret_cast<const float4*>(s_dot);
    float4* ob4 = reinterpret_cast<float4*>(out + (size_t)b * T_LEN);
#pragma unroll
    for (int k = 0; k < 2; k++) {
        const int u4 = k * 256 + tid;   // float4 index within row (0..511)
        const int c  = u4 >> 3;         // 8 float4 per chunk
        const float P = sP[c];
        const float S = sS[c];
        const float4 q = sd4[u4];
        ob4[u4] = make_float4(P + S * q.x, P + S * q.y,
                              P + S * q.z, P + S * q.w);
    }
}

// ---------------------------------------------------------------------------
extern "C" void kernel_launch(void* const* d_in, const int* in_sizes, int n_in,
                              void* d_out, int out_size)
{
    const float* x  = (const float*)d_in[0];   // (B, T, NB) fp32
    const float* qb = (const float*)d_in[1];   // (NB,)
    const float* cs = (const float*)d_in[2];   // (NB, 1)
    float* out      = (float*)d_out;           // (B, T) fp32

    const int B = out_size / T_LEN;
    fused_dequant<<<B, 256>>>(reinterpret_cast<const float4*>(x), qb, cs, out);
}